// round 14
// baseline (speedup 1.0000x reference)
#include <cuda_runtime.h>
#include <cuda_fp16.h>
#include <math.h>
#include <stdint.h>

#define SEQ    4096
#define DIM    1024
#define HEADS  16
#define DHEAD  64
#define QKV_N  3072
#define LN_EPS 1e-6f
#define ATT_SCALE 0.03125f             // DIM^-0.5
#define Q_PRESCALE (0.03125f * 1.44269504f)   // scale * log2(e)

__device__ __half g_xn   [SEQ * DIM];
__device__ __half g_qkv  [SEQ * QKV_N];
__device__ __half g_attn [SEQ * DIM];
__device__ __half g_wqkvT[QKV_N * DIM];
__device__ __half g_woutT[DIM * DIM];

// ---------------- helpers ----------------
__device__ __forceinline__ uint32_t smem_u32(const void* p) {
    uint32_t a;
    asm("{ .reg .u64 t; cvta.to.shared.u64 t, %1; cvt.u32.u64 %0, t; }" : "=r"(a) : "l"(p));
    return a;
}
__device__ __forceinline__ void mma_f16(float* d, uint32_t a0, uint32_t a1, uint32_t a2, uint32_t a3,
                                        uint32_t b0, uint32_t b1) {
    asm volatile("mma.sync.aligned.m16n8k16.row.col.f32.f16.f16.f32 "
        "{%0,%1,%2,%3}, {%4,%5,%6,%7}, {%8,%9}, {%0,%1,%2,%3};"
        : "+f"(d[0]), "+f"(d[1]), "+f"(d[2]), "+f"(d[3])
        : "r"(a0), "r"(a1), "r"(a2), "r"(a3), "r"(b0), "r"(b1));
}
__device__ __forceinline__ void ldsm4(uint32_t& r0, uint32_t& r1, uint32_t& r2, uint32_t& r3,
                                      uint32_t addr) {
    asm volatile("ldmatrix.sync.aligned.m8n8.x4.shared.b16 {%0,%1,%2,%3}, [%4];"
        : "=r"(r0), "=r"(r1), "=r"(r2), "=r"(r3) : "r"(addr));
}
__device__ __forceinline__ void ldsm4t(uint32_t& r0, uint32_t& r1, uint32_t& r2, uint32_t& r3,
                                       uint32_t addr) {
    asm volatile("ldmatrix.sync.aligned.m8n8.x4.trans.shared.b16 {%0,%1,%2,%3}, [%4];"
        : "=r"(r0), "=r"(r1), "=r"(r2), "=r"(r3) : "r"(addr));
}
__device__ __forceinline__ void ldsm2t(uint32_t& r0, uint32_t& r1, uint32_t addr) {
    asm volatile("ldmatrix.sync.aligned.m8n8.x2.trans.shared.b16 {%0,%1}, [%2];"
        : "=r"(r0), "=r"(r1) : "r"(addr));
}
__device__ __forceinline__ void cp16(uint32_t dst, const void* src) {
    asm volatile("cp.async.ca.shared.global [%0], [%1], 16;" :: "r"(dst), "l"(src) : "memory");
}
#define CP_COMMIT() asm volatile("cp.async.commit_group;" ::: "memory")
#define CP_WAIT(n)  asm volatile("cp.async.wait_group %0;" :: "n"(n) : "memory")

// P = 2^sacc (sacc already in log2 domain via pre-scaled Q); fp16x2 MUFU
__device__ __forceinline__ uint32_t exp2h2(float x, float y) {
    __half2 h = h2exp2(__floats2half2_rn(x, y));
    return *reinterpret_cast<uint32_t*>(&h);
}

// ---------------- LayerNorm (fp16 output) ----------------
__global__ void __launch_bounds__(256) ln_kernel(
    const float* __restrict__ x, const float* __restrict__ g,
    const float* __restrict__ b, __half* __restrict__ o)
{
    const int row = blockIdx.x, t = threadIdx.x;
    float4 v = ((const float4*)(x + (size_t)row * DIM))[t];
    float s = v.x + v.y + v.z + v.w;
    float s2 = v.x*v.x + v.y*v.y + v.z*v.z + v.w*v.w;
    #pragma unroll
    for (int off = 16; off > 0; off >>= 1) {
        s  += __shfl_down_sync(0xffffffffu, s, off);
        s2 += __shfl_down_sync(0xffffffffu, s2, off);
    }
    __shared__ float ss[8], ss2[8];
    if ((t & 31) == 0) { ss[t >> 5] = s; ss2[t >> 5] = s2; }
    __syncthreads();
    if (t == 0) {
        float a = 0.f, a2 = 0.f;
        #pragma unroll
        for (int i = 0; i < 8; i++) { a += ss[i]; a2 += ss2[i]; }
        ss[0] = a; ss2[0] = a2;
    }
    __syncthreads();
    const float mean = ss[0] * (1.0f / DIM);
    const float rstd = rsqrtf(ss2[0] * (1.0f / DIM) - mean * mean + LN_EPS);
    float4 gv = ((const float4*)g)[t], bv = ((const float4*)b)[t];
    __half2* op = (__half2*)(o + (size_t)row * DIM + 4 * t);
    op[0] = __floats2half2_rn((v.x - mean) * rstd * gv.x + bv.x,
                              (v.y - mean) * rstd * gv.y + bv.y);
    op[1] = __floats2half2_rn((v.z - mean) * rstd * gv.z + bv.z,
                              (v.w - mean) * rstd * gv.w + bv.w);
}

// ---------------- transpose + fp16 round: out[c][r] = in[r][c] ----------------
__global__ void __launch_bounds__(256) transpose_kernel(
    const float* __restrict__ in, __half* __restrict__ out, int cols, int rows)
{
    __shared__ float tile[32][33];
    const int bx = blockIdx.x * 32, by = blockIdx.y * 32;
    const int tx = threadIdx.x, ty = threadIdx.y;
    #pragma unroll
    for (int j = 0; j < 32; j += 8)
        tile[ty + j][tx] = in[(size_t)(by + ty + j) * cols + bx + tx];
    __syncthreads();
    #pragma unroll
    for (int j = 0; j < 32; j += 8)
        out[(size_t)(bx + ty + j) * rows + by + tx] = __float2half_rn(tile[tx][ty + j]);
}

// ---------------- fp16 mma.sync GEMM: C = A @ Bt^T ----------------
// Block 128x128, BK=32, cp.async 3-stage pipeline, ONE barrier per stage.
// Wait placed BEFORE this stage's commit => CP_WAIT(1) guarantees stage kc done.
#define G_STR 40                  // halves per row (32 + 8 pad)
#define G_BUF (128 * G_STR)       // 5120 halves per buffer
#define G_SMEM (6 * G_BUF * 2)    // 3 stages x (A+B) = 61440 B

__global__ void __launch_bounds__(256) gemm_mma(
    const __half* __restrict__ A, const __half* __restrict__ Bt,
    float* __restrict__ Cf, __half* __restrict__ Ch,
    int K, int N, const float* __restrict__ bias,
    float q_scale, int q_cols)
{
    extern __shared__ __half smh[];
    const uint32_t as_u = smem_u32(smh), bs_u = smem_u32(smh + 3 * G_BUF);

    const int tid = threadIdx.x, lane = tid & 31, wid = tid >> 5;
    const int m0 = blockIdx.y * 128, n0 = blockIdx.x * 128;
    const int wr = (wid >> 2) * 64, wc = (wid & 3) * 32;
    const int r = lane >> 2, c = lane & 3;
    const int lrow = lane & 7, ltile = lane >> 3;
    const int nkc = K >> 5;

    float acc[4][4][4];
    #pragma unroll
    for (int i = 0; i < 4; i++)
        #pragma unroll
        for (int j = 0; j < 4; j++)
            #pragma unroll
            for (int q = 0; q < 4; q++) acc[i][j][q] = 0.f;

    // prologue: stages 0 and 1 (one commit each)
    #pragma unroll
    for (int s = 0; s < 2; s++) {
        const uint32_t bo = (uint32_t)(s * G_BUF) * 2;
        #pragma unroll
        for (int l = 0; l < 2; l++) {
            const int id = tid + 256 * l, row = id >> 2, cq = id & 3;
            cp16(as_u + bo + (uint32_t)(row * G_STR + cq * 8) * 2,
                 A  + (size_t)(m0 + row) * K + s * 32 + cq * 8);
            cp16(bs_u + bo + (uint32_t)(row * G_STR + cq * 8) * 2,
                 Bt + (size_t)(n0 + row) * K + s * 32 + cq * 8);
        }
        CP_COMMIT();
    }

    for (int kc = 0; kc < nkc; kc++) {
        // commits so far = kc + 2; allow 1 pending => groups 0..kc complete
        CP_WAIT(1);
        __syncthreads();     // data visible CTA-wide; buf (kc+2)%3 free to write
        if (kc + 2 < nkc) {
            const uint32_t bo = (uint32_t)(((kc + 2) % 3) * G_BUF) * 2;
            #pragma unroll
            for (int l = 0; l < 2; l++) {
                const int id = tid + 256 * l, row = id >> 2, cq = id & 3;
                cp16(as_u + bo + (uint32_t)(row * G_STR + cq * 8) * 2,
                     A  + (size_t)(m0 + row) * K + (kc + 2) * 32 + cq * 8);
                cp16(bs_u + bo + (uint32_t)(row * G_STR + cq * 8) * 2,
                     Bt + (size_t)(n0 + row) * K + (kc + 2) * 32 + cq * 8);
            }
        }
        CP_COMMIT();         // always commit: keeps group count aligned
        const uint32_t ab = as_u + (uint32_t)((kc % 3) * G_BUF) * 2;
        const uint32_t bb = bs_u + (uint32_t)((kc % 3) * G_BUF) * 2;
        #pragma unroll
        for (int kk = 0; kk < 2; kk++) {
            const int k0 = kk * 16;
            uint32_t a[4][4];
            #pragma unroll
            for (int mt = 0; mt < 4; mt++) {
                const int mb = wr + mt * 16;
                ldsm4(a[mt][0], a[mt][1], a[mt][2], a[mt][3],
                      ab + (uint32_t)(((mb + (ltile & 1) * 8 + lrow) * G_STR
                                       + k0 + (ltile >> 1) * 8) * 2));
            }
            #pragma unroll
            for (int g = 0; g < 2; g++) {
                uint32_t b0a, b1a, b0b, b1b;
                ldsm4(b0a, b1a, b0b, b1b,
                      bb + (uint32_t)(((wc + g * 16 + (ltile >> 1) * 8 + lrow) * G_STR
                                       + k0 + (ltile & 1) * 8) * 2));
                #pragma unroll
                for (int mt = 0; mt < 4; mt++) {
                    mma_f16(acc[mt][g * 2 + 0], a[mt][0], a[mt][1], a[mt][2], a[mt][3], b0a, b1a);
                    mma_f16(acc[mt][g * 2 + 1], a[mt][0], a[mt][1], a[mt][2], a[mt][3], b0b, b1b);
                }
            }
        }
    }

    const float sc = (n0 < q_cols) ? q_scale : 1.0f;   // uniform per CTA
    #pragma unroll
    for (int mt = 0; mt < 4; mt++) {
        #pragma unroll
        for (int nt = 0; nt < 4; nt++) {
            const int row = m0 + wr + mt * 16 + r;
            const int col = n0 + wc + nt * 8 + 2 * c;
            if (Ch) {
                *(__half2*)(Ch + (size_t)row * N + col) =
                    __floats2half2_rn(acc[mt][nt][0] * sc, acc[mt][nt][1] * sc);
                *(__half2*)(Ch + (size_t)(row + 8) * N + col) =
                    __floats2half2_rn(acc[mt][nt][2] * sc, acc[mt][nt][3] * sc);
            } else {
                const float b0 = bias[col], b1 = bias[col + 1];
                float2 v;
                v.x = acc[mt][nt][0] + b0; v.y = acc[mt][nt][1] + b1;
                *(float2*)(Cf + (size_t)row * N + col) = v;
                v.x = acc[mt][nt][2] + b0; v.y = acc[mt][nt][3] + b1;
                *(float2*)(Cf + (size_t)(row + 8) * N + col) = v;
            }
        }
    }
}

// ---------------- fp16 mma.sync attention ----------------
// CTA = (head, 128 queries); key tile 64; 8 warps x 16 q-rows.
// Q pre-scaled by scale*log2e -> P = exp2(S) via fp16x2 MUFU.
// Row sums via tensor core (V ones column). 3-stage cp.async K/V pipeline,
// ONE barrier per key tile; CP_WAIT(1) before this stage's commit.
#define A_STR 72                         // halves per row (64 + 8 pad)
#define AQS 0                            // Q [128][72]
#define AKS (128 * A_STR)                // K [3][64][72]
#define AVS (AKS + 3 * 64 * A_STR)       // V [3][64][72]
#define A_TOTH (AVS + 3 * 64 * A_STR)    // 36864 halves
#define A_SMEM (A_TOTH * 2)              // 73728 B
#define A_KVB (64 * A_STR)               // halves per K/V buffer

__global__ void __launch_bounds__(256, 2) attn_mma(
    const __half* __restrict__ qkv, __half* __restrict__ out)
{
    extern __shared__ __half smh[];
    const uint32_t sb_u = smem_u32(smh);

    const int tid = threadIdx.x, lane = tid & 31, wid = tid >> 5;
    const int h = blockIdx.y, i0 = blockIdx.x * 128;
    const int m0 = wid * 16;
    const int r = lane >> 2, c = lane & 3;
    const int lrow = lane & 7, ltile = lane >> 3;

    // one-time V padding init: col 64 = 1.0, cols 65..71 = 0 (all 3 buffers)
    for (int i = tid; i < 3 * 64; i += 256) {
        const int buf = i >> 6, row = i & 63;
        __half* p = smh + AVS + buf * A_KVB + row * A_STR + 64;
        p[0] = __float2half(1.0f);
        #pragma unroll
        for (int q = 1; q < 8; q++) p[q] = __float2half(0.0f);
    }

    // prologue: Q + K/V stage 0 (group 0), K/V stage 1 (group 1)
    #pragma unroll
    for (int l = 0; l < 4; l++) {
        const int id = tid + 256 * l, row = id >> 3, cq = id & 7;
        cp16(sb_u + (uint32_t)(row * A_STR + cq * 8) * 2,
             qkv + (size_t)(i0 + row) * QKV_N + h * DHEAD + cq * 8);
    }
    #pragma unroll
    for (int s = 0; s < 2; s++) {
        #pragma unroll
        for (int l = 0; l < 2; l++) {
            const int id = tid + 256 * l, row = id >> 3, cq = id & 7;
            cp16(sb_u + (uint32_t)(AKS + s * A_KVB + row * A_STR + cq * 8) * 2,
                 qkv + (size_t)(s * 64 + row) * QKV_N + 1024 + h * DHEAD + cq * 8);
            cp16(sb_u + (uint32_t)(AVS + s * A_KVB + row * A_STR + cq * 8) * 2,
                 qkv + (size_t)(s * 64 + row) * QKV_N + 2048 + h * DHEAD + cq * 8);
        }
        CP_COMMIT();
    }

    float oacc[8][4], osum[4];
    #pragma unroll
    for (int nt = 0; nt < 8; nt++)
        #pragma unroll
        for (int q = 0; q < 4; q++) oacc[nt][q] = 0.f;
    #pragma unroll
    for (int q = 0; q < 4; q++) osum[q] = 0.f;

    for (int t = 0; t < 64; t++) {
        // commits so far = t + 2; allow 1 pending => groups 0..t complete
        CP_WAIT(1);
        __syncthreads();     // visible CTA-wide; buf (t+2)%3 free to write
        if (t + 2 < 64) {
            const int nb = (t + 2) % 3;
            const int j1 = (t + 2) * 64;
            #pragma unroll
            for (int l = 0; l < 2; l++) {
                const int id = tid + 256 * l, row = id >> 3, cq = id & 7;
                cp16(sb_u + (uint32_t)(AKS + nb * A_KVB + row * A_STR + cq * 8) * 2,
                     qkv + (size_t)(j1 + row) * QKV_N + 1024 + h * DHEAD + cq * 8);
                cp16(sb_u + (uint32_t)(AVS + nb * A_KVB + row * A_STR + cq * 8) * 2,
                     qkv + (size_t)(j1 + row) * QKV_N + 2048 + h * DHEAD + cq * 8);
            }
        }
        CP_COMMIT();         // always commit

        const int cur = t % 3;
        const uint32_t ks = sb_u + (uint32_t)(AKS + cur * A_KVB) * 2;
        const uint32_t vs = sb_u + (uint32_t)(AVS + cur * A_KVB) * 2;

        // ---- S = Qs @ K^T (log2 domain; Q pre-scaled) ----
        float sacc[8][4];
        #pragma unroll
        for (int nt = 0; nt < 8; nt++)
            #pragma unroll
            for (int q = 0; q < 4; q++) sacc[nt][q] = 0.f;
        #pragma unroll
        for (int kk = 0; kk < 4; kk++) {
            const int k0 = kk * 16;
            uint32_t a0, a1, a2, a3;
            ldsm4(a0, a1, a2, a3,
                  sb_u + (uint32_t)(((m0 + (ltile & 1) * 8 + lrow) * A_STR
                                     + k0 + (ltile >> 1) * 8) * 2));
            #pragma unroll
            for (int g = 0; g < 4; g++) {
                uint32_t b0a, b1a, b0b, b1b;
                ldsm4(b0a, b1a, b0b, b1b,
                      ks + (uint32_t)(((g * 16 + (ltile >> 1) * 8 + lrow) * A_STR
                                       + k0 + (ltile & 1) * 8) * 2));
                mma_f16(sacc[g * 2 + 0], a0, a1, a2, a3, b0a, b1a);
                mma_f16(sacc[g * 2 + 1], a0, a1, a2, a3, b0b, b1b);
            }
        }

        // ---- P = exp2(S) via fp16x2 MUFU; P regs are PV A-fragments ----
        uint32_t ph[8][2];
        #pragma unroll
        for (int nt = 0; nt < 8; nt++) {
            ph[nt][0] = exp2h2(sacc[nt][0], sacc[nt][1]);
            ph[nt][1] = exp2h2(sacc[nt][2], sacc[nt][3]);
        }

        // ---- O += P @ V (8 n-tiles) + row-sum tile (V ones column) ----
        #pragma unroll
        for (int kk2 = 0; kk2 < 4; kk2++) {
            const int k0 = kk2 * 16;
            const uint32_t a0 = ph[2 * kk2][0],     a1 = ph[2 * kk2][1];
            const uint32_t a2 = ph[2 * kk2 + 1][0], a3 = ph[2 * kk2 + 1][1];
            #pragma unroll
            for (int g = 0; g < 4; g++) {
                uint32_t b0a, b1a, b0b, b1b;
                ldsm4t(b0a, b1a, b0b, b1b,
                       vs + (uint32_t)(((k0 + (ltile & 1) * 8 + lrow) * A_STR
                                        + (g * 2 + (ltile >> 1)) * 8) * 2));
                mma_f16(oacc[g * 2 + 0], a0, a1, a2, a3, b0a, b1a);
                mma_f16(oacc[g * 2 + 1], a0, a1, a2, a3, b0b, b1b);
            }
            uint32_t s0, s1;
            ldsm2t(s0, s1, vs + (uint32_t)(((k0 + (lane & 15)) * A_STR + 64) * 2));
            mma_f16(osum, a0, a1, a2, a3, s0, s1);
        }
    }

    // ---- row sums live in osum col 64 (c==0 lanes); broadcast within quad ----
    const float l0 = __shfl_sync(0xffffffffu, osum[0], lane & ~3);
    const float l1 = __shfl_sync(0xffffffffu, osum[2], lane & ~3);
    const float inv0 = 1.0f / l0, inv1 = 1.0f / l1;

    // ---- normalize + fp16 store (feeds out-proj) ----
    const int row0 = i0 + m0 + r;
    #pragma unroll
    for (int nt = 0; nt < 8; nt++) {
        const int col = h * DHEAD + nt * 8 + 2 * c;
        *(__half2*)(out + (size_t)row0 * DIM + col) =
            __floats2half2_rn(oacc[nt][0] * inv0, oacc[nt][1] * inv0);
        *(__half2*)(out + (size_t)(row0 + 8) * DIM + col) =
            __floats2half2_rn(oacc[nt][2] * inv1, oacc[nt][3] * inv1);
    }
}

// ---------------- launcher ----------------
extern "C" void kernel_launch(void* const* d_in, const int* in_sizes, int n_in,
                              void* d_out, int out_size)
{
    const float* x     = (const float*)d_in[0];
    const float* ln_s  = (const float*)d_in[1];
    const float* ln_b  = (const float*)d_in[2];
    const float* w_qkv = (const float*)d_in[3];
    const float* w_out = (const float*)d_in[4];
    const float* b_out = (const float*)d_in[5];
    float* out = (float*)d_out;

    __half *xn, *qkv, *attn, *wqkvT, *woutT;
    cudaGetSymbolAddress((void**)&xn,    g_xn);
    cudaGetSymbolAddress((void**)&qkv,   g_qkv);
    cudaGetSymbolAddress((void**)&attn,  g_attn);
    cudaGetSymbolAddress((void**)&wqkvT, g_wqkvT);
    cudaGetSymbolAddress((void**)&woutT, g_woutT);

    cudaFuncSetAttribute(gemm_mma, cudaFuncAttributeMaxDynamicSharedMemorySize, G_SMEM);
    cudaFuncSetAttribute(attn_mma, cudaFuncAttributeMaxDynamicSharedMemorySize, A_SMEM);

    ln_kernel<<<SEQ, 256>>>(x, ln_s, ln_b, xn);
    transpose_kernel<<<dim3(QKV_N / 32, DIM / 32), dim3(32, 8)>>>(w_qkv, wqkvT, QKV_N, DIM);
    transpose_kernel<<<dim3(DIM / 32, DIM / 32),   dim3(32, 8)>>>(w_out, woutT, DIM, DIM);

    // QKV projection -> half; Q columns (n<1024) pre-scaled by scale*log2e
    gemm_mma<<<dim3(QKV_N / 128, SEQ / 128), 256, G_SMEM>>>(
        xn, wqkvT, nullptr, qkv, DIM, QKV_N, nullptr, Q_PRESCALE, 1024);
    attn_mma<<<dim3(SEQ / 128, HEADS), 256, A_SMEM>>>(qkv, attn);
    // output projection -> fp32 + bias
    gemm_mma<<<dim3(DIM / 128, SEQ / 128), 256, G_SMEM>>>(
        attn, woutT, out, nullptr, DIM, DIM, b_out, 1.0f, 0);
}

// round 16
// speedup vs baseline: 1.0102x; 1.0102x over previous
#include <cuda_runtime.h>
#include <cuda_fp16.h>
#include <math.h>
#include <stdint.h>

#define SEQ    4096
#define DIM    1024
#define HEADS  16
#define DHEAD  64
#define QKV_N  3072
#define LN_EPS 1e-6f
#define ATT_SCALE 0.03125f             // DIM^-0.5
#define Q_PRESCALE (0.03125f * 1.44269504f)   // scale * log2(e)

__device__ __half g_xn   [SEQ * DIM];
__device__ __half g_qkv  [SEQ * QKV_N];
__device__ __half g_attn [SEQ * DIM];
__device__ __half g_wqkvT[QKV_N * DIM];
__device__ __half g_woutT[DIM * DIM];

// ---------------- helpers ----------------
__device__ __forceinline__ uint32_t smem_u32(const void* p) {
    uint32_t a;
    asm("{ .reg .u64 t; cvta.to.shared.u64 t, %1; cvt.u32.u64 %0, t; }" : "=r"(a) : "l"(p));
    return a;
}
__device__ __forceinline__ void mma_f16(float* d, uint32_t a0, uint32_t a1, uint32_t a2, uint32_t a3,
                                        uint32_t b0, uint32_t b1) {
    asm volatile("mma.sync.aligned.m16n8k16.row.col.f32.f16.f16.f32 "
        "{%0,%1,%2,%3}, {%4,%5,%6,%7}, {%8,%9}, {%0,%1,%2,%3};"
        : "+f"(d[0]), "+f"(d[1]), "+f"(d[2]), "+f"(d[3])
        : "r"(a0), "r"(a1), "r"(a2), "r"(a3), "r"(b0), "r"(b1));
}
__device__ __forceinline__ void ldsm4(uint32_t* r, uint32_t addr) {
    asm volatile("ldmatrix.sync.aligned.m8n8.x4.shared.b16 {%0,%1,%2,%3}, [%4];"
        : "=r"(r[0]), "=r"(r[1]), "=r"(r[2]), "=r"(r[3]) : "r"(addr));
}
__device__ __forceinline__ void ldsm4t(uint32_t* r, uint32_t addr) {
    asm volatile("ldmatrix.sync.aligned.m8n8.x4.trans.shared.b16 {%0,%1,%2,%3}, [%4];"
        : "=r"(r[0]), "=r"(r[1]), "=r"(r[2]), "=r"(r[3]) : "r"(addr));
}
__device__ __forceinline__ void ldsm2t(uint32_t* r, uint32_t addr) {
    asm volatile("ldmatrix.sync.aligned.m8n8.x2.trans.shared.b16 {%0,%1}, [%2];"
        : "=r"(r[0]), "=r"(r[1]) : "r"(addr));
}
__device__ __forceinline__ void cp16(uint32_t dst, const void* src) {
    asm volatile("cp.async.ca.shared.global [%0], [%1], 16;" :: "r"(dst), "l"(src) : "memory");
}
#define CP_COMMIT() asm volatile("cp.async.commit_group;" ::: "memory")
#define CP_WAIT(n)  asm volatile("cp.async.wait_group %0;" :: "n"(n) : "memory")

// P = 2^sacc (sacc already in log2 domain via pre-scaled Q); fp16x2 MUFU
__device__ __forceinline__ uint32_t exp2h2(float x, float y) {
    __half2 h = h2exp2(__floats2half2_rn(x, y));
    return *reinterpret_cast<uint32_t*>(&h);
}

// ---------------- LayerNorm (fp16 output) ----------------
__global__ void __launch_bounds__(256) ln_kernel(
    const float* __restrict__ x, const float* __restrict__ g,
    const float* __restrict__ b, __half* __restrict__ o)
{
    const int row = blockIdx.x, t = threadIdx.x;
    float4 v = ((const float4*)(x + (size_t)row * DIM))[t];
    float s = v.x + v.y + v.z + v.w;
    float s2 = v.x*v.x + v.y*v.y + v.z*v.z + v.w*v.w;
    #pragma unroll
    for (int off = 16; off > 0; off >>= 1) {
        s  += __shfl_down_sync(0xffffffffu, s, off);
        s2 += __shfl_down_sync(0xffffffffu, s2, off);
    }
    __shared__ float ss[8], ss2[8];
    if ((t & 31) == 0) { ss[t >> 5] = s; ss2[t >> 5] = s2; }
    __syncthreads();
    if (t == 0) {
        float a = 0.f, a2 = 0.f;
        #pragma unroll
        for (int i = 0; i < 8; i++) { a += ss[i]; a2 += ss2[i]; }
        ss[0] = a; ss2[0] = a2;
    }
    __syncthreads();
    const float mean = ss[0] * (1.0f / DIM);
    const float rstd = rsqrtf(ss2[0] * (1.0f / DIM) - mean * mean + LN_EPS);
    float4 gv = ((const float4*)g)[t], bv = ((const float4*)b)[t];
    __half2* op = (__half2*)(o + (size_t)row * DIM + 4 * t);
    op[0] = __floats2half2_rn((v.x - mean) * rstd * gv.x + bv.x,
                              (v.y - mean) * rstd * gv.y + bv.y);
    op[1] = __floats2half2_rn((v.z - mean) * rstd * gv.z + bv.z,
                              (v.w - mean) * rstd * gv.w + bv.w);
}

// ---------------- transpose + fp16 round: out[c][r] = in[r][c] ----------------
__global__ void __launch_bounds__(256) transpose_kernel(
    const float* __restrict__ in, __half* __restrict__ out, int cols, int rows)
{
    __shared__ float tile[32][33];
    const int bx = blockIdx.x * 32, by = blockIdx.y * 32;
    const int tx = threadIdx.x, ty = threadIdx.y;
    #pragma unroll
    for (int j = 0; j < 32; j += 8)
        tile[ty + j][tx] = in[(size_t)(by + ty + j) * cols + bx + tx];
    __syncthreads();
    #pragma unroll
    for (int j = 0; j < 32; j += 8)
        out[(size_t)(bx + ty + j) * rows + by + tx] = __float2half_rn(tile[tx][ty + j]);
}

// ---------------- fp16 mma.sync GEMM: C = A @ Bt^T ----------------
// Block 128x128, BK=32, cp.async 2-stage (R12 structure), 8 warps, tile 64x32.
// Fragment loads for BOTH kk sub-steps hoisted ahead of all MMAs (reg dbuf).
#define G_STR 40                  // halves per row (32 + 8 pad)
#define G_BUF (128 * G_STR)       // 5120 halves per buffer
#define G_SMEM (4 * G_BUF * 2)    // 2 stages x (A+B) = 40960 B

__global__ void __launch_bounds__(256, 2) gemm_mma(
    const __half* __restrict__ A, const __half* __restrict__ Bt,
    float* __restrict__ Cf, __half* __restrict__ Ch,
    int K, int N, const float* __restrict__ bias,
    float q_scale, int q_cols)
{
    extern __shared__ __half smh[];
    const uint32_t as_u = smem_u32(smh), bs_u = smem_u32(smh + 2 * G_BUF);

    const int tid = threadIdx.x, lane = tid & 31, wid = tid >> 5;
    const int m0 = blockIdx.y * 128, n0 = blockIdx.x * 128;
    const int wr = (wid >> 2) * 64, wc = (wid & 3) * 32;
    const int r = lane >> 2, c = lane & 3;
    const int lrow = lane & 7, ltile = lane >> 3;
    const int nkc = K >> 5;

    float acc[4][4][4];
    #pragma unroll
    for (int i = 0; i < 4; i++)
        #pragma unroll
        for (int j = 0; j < 4; j++)
            #pragma unroll
            for (int q = 0; q < 4; q++) acc[i][j][q] = 0.f;

    #pragma unroll
    for (int l = 0; l < 2; l++) {
        const int id = tid + 256 * l, row = id >> 2, cq = id & 3;
        cp16(as_u + (uint32_t)(row * G_STR + cq * 8) * 2, A  + (size_t)(m0 + row) * K + cq * 8);
        cp16(bs_u + (uint32_t)(row * G_STR + cq * 8) * 2, Bt + (size_t)(n0 + row) * K + cq * 8);
    }
    CP_COMMIT();

    for (int kc = 0; kc < nkc; kc++) {
        if (kc + 1 < nkc) {
            const uint32_t bo = (uint32_t)(((kc + 1) & 1) * G_BUF) * 2;
            #pragma unroll
            for (int l = 0; l < 2; l++) {
                const int id = tid + 256 * l, row = id >> 2, cq = id & 3;
                cp16(as_u + bo + (uint32_t)(row * G_STR + cq * 8) * 2,
                     A  + (size_t)(m0 + row) * K + (kc + 1) * 32 + cq * 8);
                cp16(bs_u + bo + (uint32_t)(row * G_STR + cq * 8) * 2,
                     Bt + (size_t)(n0 + row) * K + (kc + 1) * 32 + cq * 8);
            }
            CP_COMMIT();
            CP_WAIT(1);
        } else {
            CP_WAIT(0);
        }
        __syncthreads();
        const uint32_t ab = as_u + (uint32_t)((kc & 1) * G_BUF) * 2;
        const uint32_t bb = bs_u + (uint32_t)((kc & 1) * G_BUF) * 2;

        // hoist ALL fragment loads for this stage (both kk) before the MMAs
        uint32_t a[2][4][4], b[2][2][4];
        #pragma unroll
        for (int kk = 0; kk < 2; kk++) {
            const int k0 = kk * 16;
            #pragma unroll
            for (int mt = 0; mt < 4; mt++) {
                const int mb = wr + mt * 16;
                ldsm4(a[kk][mt],
                      ab + (uint32_t)(((mb + (ltile & 1) * 8 + lrow) * G_STR
                                       + k0 + (ltile >> 1) * 8) * 2));
            }
            #pragma unroll
            for (int g = 0; g < 2; g++) {
                ldsm4(b[kk][g],
                      bb + (uint32_t)(((wc + g * 16 + (ltile >> 1) * 8 + lrow) * G_STR
                                       + k0 + (ltile & 1) * 8) * 2));
            }
        }
        #pragma unroll
        for (int kk = 0; kk < 2; kk++) {
            #pragma unroll
            for (int g = 0; g < 2; g++) {
                #pragma unroll
                for (int mt = 0; mt < 4; mt++) {
                    mma_f16(acc[mt][g * 2 + 0], a[kk][mt][0], a[kk][mt][1], a[kk][mt][2], a[kk][mt][3],
                            b[kk][g][0], b[kk][g][1]);
                    mma_f16(acc[mt][g * 2 + 1], a[kk][mt][0], a[kk][mt][1], a[kk][mt][2], a[kk][mt][3],
                            b[kk][g][2], b[kk][g][3]);
                }
            }
        }
        __syncthreads();
    }

    const float sc = (n0 < q_cols) ? q_scale : 1.0f;   // uniform per CTA
    #pragma unroll
    for (int mt = 0; mt < 4; mt++) {
        #pragma unroll
        for (int nt = 0; nt < 4; nt++) {
            const int row = m0 + wr + mt * 16 + r;
            const int col = n0 + wc + nt * 8 + 2 * c;
            if (Ch) {
                *(__half2*)(Ch + (size_t)row * N + col) =
                    __floats2half2_rn(acc[mt][nt][0] * sc, acc[mt][nt][1] * sc);
                *(__half2*)(Ch + (size_t)(row + 8) * N + col) =
                    __floats2half2_rn(acc[mt][nt][2] * sc, acc[mt][nt][3] * sc);
            } else {
                const float b0 = bias[col], b1 = bias[col + 1];
                float2 v;
                v.x = acc[mt][nt][0] + b0; v.y = acc[mt][nt][1] + b1;
                *(float2*)(Cf + (size_t)row * N + col) = v;
                v.x = acc[mt][nt][2] + b0; v.y = acc[mt][nt][3] + b1;
                *(float2*)(Cf + (size_t)(row + 8) * N + col) = v;
            }
        }
    }
}

// ---------------- fp16 mma.sync attention ----------------
// R12 structure (2-stage, 2 barriers/tile) + register-double-buffered fragments:
// S-phase prefetches Q/K frags one kk ahead; PV-phase prefetches V frags one
// kk2 ahead. Q pre-scaled -> P=exp2(S) fp16x2 MUFU; row sums via V ones column.
#define A_STR 72                         // halves per row (64 + 8 pad)
#define AQS 0                            // Q [128][72]
#define AKS (128 * A_STR)                // K [2][64][72]
#define AVS (AKS + 2 * 64 * A_STR)       // V [2][64][72]
#define A_TOTH (AVS + 2 * 64 * A_STR)    // 27648 halves
#define A_SMEM (A_TOTH * 2)              // 55296 B
#define A_KVB (64 * A_STR)               // halves per K/V buffer

__global__ void __launch_bounds__(256, 2) attn_mma(
    const __half* __restrict__ qkv, __half* __restrict__ out)
{
    extern __shared__ __half smh[];
    const uint32_t sb_u = smem_u32(smh);

    const int tid = threadIdx.x, lane = tid & 31, wid = tid >> 5;
    const int h = blockIdx.y, i0 = blockIdx.x * 128;
    const int m0 = wid * 16;
    const int r = lane >> 2, c = lane & 3;
    const int lrow = lane & 7, ltile = lane >> 3;

    // one-time V padding init: col 64 = 1.0, cols 65..71 = 0 (both buffers)
    for (int i = tid; i < 2 * 64; i += 256) {
        const int buf = i >> 6, row = i & 63;
        __half* p = smh + AVS + buf * A_KVB + row * A_STR + 64;
        p[0] = __float2half(1.0f);
        #pragma unroll
        for (int q = 1; q < 8; q++) p[q] = __float2half(0.0f);
    }

    // preload Q + K/V tile 0
    #pragma unroll
    for (int l = 0; l < 4; l++) {
        const int id = tid + 256 * l, row = id >> 3, cq = id & 7;
        cp16(sb_u + (uint32_t)(row * A_STR + cq * 8) * 2,
             qkv + (size_t)(i0 + row) * QKV_N + h * DHEAD + cq * 8);
    }
    #pragma unroll
    for (int l = 0; l < 2; l++) {
        const int id = tid + 256 * l, row = id >> 3, cq = id & 7;
        cp16(sb_u + (uint32_t)(AKS + row * A_STR + cq * 8) * 2,
             qkv + (size_t)row * QKV_N + 1024 + h * DHEAD + cq * 8);
        cp16(sb_u + (uint32_t)(AVS + row * A_STR + cq * 8) * 2,
             qkv + (size_t)row * QKV_N + 2048 + h * DHEAD + cq * 8);
    }
    CP_COMMIT();

    float oacc[8][4], osum[4];
    #pragma unroll
    for (int nt = 0; nt < 8; nt++)
        #pragma unroll
        for (int q = 0; q < 4; q++) oacc[nt][q] = 0.f;
    #pragma unroll
    for (int q = 0; q < 4; q++) osum[q] = 0.f;

    for (int t = 0; t < 64; t++) {
        const int cur = t & 1;
        if (t + 1 < 64) {
            const int nb = cur ^ 1;
            const int j1 = (t + 1) * 64;
            #pragma unroll
            for (int l = 0; l < 2; l++) {
                const int id = tid + 256 * l, row = id >> 3, cq = id & 7;
                cp16(sb_u + (uint32_t)(AKS + nb * A_KVB + row * A_STR + cq * 8) * 2,
                     qkv + (size_t)(j1 + row) * QKV_N + 1024 + h * DHEAD + cq * 8);
                cp16(sb_u + (uint32_t)(AVS + nb * A_KVB + row * A_STR + cq * 8) * 2,
                     qkv + (size_t)(j1 + row) * QKV_N + 2048 + h * DHEAD + cq * 8);
            }
            CP_COMMIT();
            CP_WAIT(1);
        } else {
            CP_WAIT(0);
        }
        __syncthreads();

        const uint32_t ks = sb_u + (uint32_t)(AKS + cur * A_KVB) * 2;
        const uint32_t vs = sb_u + (uint32_t)(AVS + cur * A_KVB) * 2;

        // ---- S = Qs @ K^T, frag prefetch one kk ahead ----
        float sacc[8][4];
        #pragma unroll
        for (int nt = 0; nt < 8; nt++)
            #pragma unroll
            for (int q = 0; q < 4; q++) sacc[nt][q] = 0.f;

        uint32_t qf[2][4], kf[2][4][4];
        ldsm4(qf[0], sb_u + (uint32_t)(((m0 + (ltile & 1) * 8 + lrow) * A_STR
                                        + (ltile >> 1) * 8) * 2));
        #pragma unroll
        for (int g = 0; g < 4; g++)
            ldsm4(kf[0][g], ks + (uint32_t)(((g * 16 + (ltile >> 1) * 8 + lrow) * A_STR
                                             + (ltile & 1) * 8) * 2));
        #pragma unroll
        for (int kk = 0; kk < 4; kk++) {
            const int cb = kk & 1, nb2 = cb ^ 1;
            if (kk < 3) {
                const int k1 = (kk + 1) * 16;
                ldsm4(qf[nb2], sb_u + (uint32_t)(((m0 + (ltile & 1) * 8 + lrow) * A_STR
                                                  + k1 + (ltile >> 1) * 8) * 2));
                #pragma unroll
                for (int g = 0; g < 4; g++)
                    ldsm4(kf[nb2][g], ks + (uint32_t)(((g * 16 + (ltile >> 1) * 8 + lrow) * A_STR
                                                       + k1 + (ltile & 1) * 8) * 2));
            }
            #pragma unroll
            for (int g = 0; g < 4; g++) {
                mma_f16(sacc[g * 2 + 0], qf[cb][0], qf[cb][1], qf[cb][2], qf[cb][3],
                        kf[cb][g][0], kf[cb][g][1]);
                mma_f16(sacc[g * 2 + 1], qf[cb][0], qf[cb][1], qf[cb][2], qf[cb][3],
                        kf[cb][g][2], kf[cb][g][3]);
            }
        }

        // ---- P = exp2(S) via fp16x2 MUFU; P regs are PV A-fragments ----
        uint32_t ph[8][2];
        #pragma unroll
        for (int nt = 0; nt < 8; nt++) {
            ph[nt][0] = exp2h2(sacc[nt][0], sacc[nt][1]);
            ph[nt][1] = exp2h2(sacc[nt][2], sacc[nt][3]);
        }

        // ---- O += P @ V + row-sum tile, V-frag prefetch one kk2 ahead ----
        uint32_t vf[2][4][4], sf[2][2];
        #pragma unroll
        for (int g = 0; g < 4; g++)
            ldsm4t(vf[0][g], vs + (uint32_t)((((ltile & 1) * 8 + lrow) * A_STR
                                              + (g * 2 + (ltile >> 1)) * 8) * 2));
        ldsm2t(sf[0], vs + (uint32_t)(((lane & 15) * A_STR + 64) * 2));
        #pragma unroll
        for (int kk2 = 0; kk2 < 4; kk2++) {
            const int cb = kk2 & 1, nb2 = cb ^ 1;
            if (kk2 < 3) {
                const int k1 = (kk2 + 1) * 16;
                #pragma unroll
                for (int g = 0; g < 4; g++)
                    ldsm4t(vf[nb2][g], vs + (uint32_t)(((k1 + (ltile & 1) * 8 + lrow) * A_STR
                                                        + (g * 2 + (ltile >> 1)) * 8) * 2));
                ldsm2t(sf[nb2], vs + (uint32_t)(((k1 + (lane & 15)) * A_STR + 64) * 2));
            }
            const uint32_t a0 = ph[2 * kk2][0],     a1 = ph[2 * kk2][1];
            const uint32_t a2 = ph[2 * kk2 + 1][0], a3 = ph[2 * kk2 + 1][1];
            #pragma unroll
            for (int g = 0; g < 4; g++) {
                mma_f16(oacc[g * 2 + 0], a0, a1, a2, a3, vf[cb][g][0], vf[cb][g][1]);
                mma_f16(oacc[g * 2 + 1], a0, a1, a2, a3, vf[cb][g][2], vf[cb][g][3]);
            }
            mma_f16(osum, a0, a1, a2, a3, sf[cb][0], sf[cb][1]);
        }
        __syncthreads();   // all warps done with buf cur -> prefetch may overwrite
    }

    // ---- row sums live in osum col 64 (c==0 lanes); broadcast within quad ----
    const float l0 = __shfl_sync(0xffffffffu, osum[0], lane & ~3);
    const float l1 = __shfl_sync(0xffffffffu, osum[2], lane & ~3);
    const float inv0 = 1.0f / l0, inv1 = 1.0f / l1;

    // ---- normalize + fp16 store (feeds out-proj) ----
    const int row0 = i0 + m0 + r;
    #pragma unroll
    for (int nt = 0; nt < 8; nt++) {
        const int col = h * DHEAD + nt * 8 + 2 * c;
        *(__half2*)(out + (size_t)row0 * DIM + col) =
            __floats2half2_rn(oacc[nt][0] * inv0, oacc[nt][1] * inv0);
        *(__half2*)(out + (size_t)(row0 + 8) * DIM + col) =
            __floats2half2_rn(oacc[nt][2] * inv1, oacc[nt][3] * inv1);
    }
}

// ---------------- launcher ----------------
extern "C" void kernel_launch(void* const* d_in, const int* in_sizes, int n_in,
                              void* d_out, int out_size)
{
    const float* x     = (const float*)d_in[0];
    const float* ln_s  = (const float*)d_in[1];
    const float* ln_b  = (const float*)d_in[2];
    const float* w_qkv = (const float*)d_in[3];
    const float* w_out = (const float*)d_in[4];
    const float* b_out = (const float*)d_in[5];
    float* out = (float*)d_out;

    __half *xn, *qkv, *attn, *wqkvT, *woutT;
    cudaGetSymbolAddress((void**)&xn,    g_xn);
    cudaGetSymbolAddress((void**)&qkv,   g_qkv);
    cudaGetSymbolAddress((void**)&attn,  g_attn);
    cudaGetSymbolAddress((void**)&wqkvT, g_wqkvT);
    cudaGetSymbolAddress((void**)&woutT, g_woutT);

    cudaFuncSetAttribute(gemm_mma, cudaFuncAttributeMaxDynamicSharedMemorySize, G_SMEM);
    cudaFuncSetAttribute(attn_mma, cudaFuncAttributeMaxDynamicSharedMemorySize, A_SMEM);

    ln_kernel<<<SEQ, 256>>>(x, ln_s, ln_b, xn);
    transpose_kernel<<<dim3(QKV_N / 32, DIM / 32), dim3(32, 8)>>>(w_qkv, wqkvT, QKV_N, DIM);
    transpose_kernel<<<dim3(DIM / 32, DIM / 32),   dim3(32, 8)>>>(w_out, woutT, DIM, DIM);

    // QKV projection -> half; Q columns (n<1024) pre-scaled by scale*log2e
    gemm_mma<<<dim3(QKV_N / 128, SEQ / 128), 256, G_SMEM>>>(
        xn, wqkvT, nullptr, qkv, DIM, QKV_N, nullptr, Q_PRESCALE, 1024);
    attn_mma<<<dim3(SEQ / 128, HEADS), 256, A_SMEM>>>(qkv, attn);
    // output projection -> fp32 + bias
    gemm_mma<<<dim3(DIM / 128, SEQ / 128), 256, G_SMEM>>>(
        attn, woutT, out, nullptr, DIM, DIM, b_out, 1.0f, 0);
}